// round 8
// baseline (speedup 1.0000x reference)
#include <cuda_runtime.h>

#define DD   256
#define NN   8192
#define EE   8191
#define ALPHA 0.2f

// ---------------- scratch (allocation-free __device__ globals, zero-init) -------
// per-output-row gather tables: out_row r = lrelu((cA*x[sA] + cB*x[sB]) @ W^T)
__device__ float g_w12[2 * DD];
__device__ float g_cA[NN];
__device__ float g_cB[NN];
__device__ int   g_sA[NN];
__device__ int   g_sB[NN];

__device__ __forceinline__ unsigned f2tf(float f) {
    unsigned r; asm("cvt.rna.tf32.f32 %0, %1;" : "=r"(r) : "f"(f)); return r;
}
__device__ __forceinline__ float tfbits(float f) { return __uint_as_float(f2tf(f)); }
__device__ __forceinline__ float lrelu(float v) { return v > 0.f ? v : ALPHA * v; }
__device__ __forceinline__ unsigned su32(const void* p) {
    return (unsigned)__cvta_generic_to_shared(p);
}
__device__ __forceinline__ float dot4(float4 a, float4 b) {
    return a.x * b.x + a.y * b.y + a.z * b.z + a.w * b.w;
}

// ---------------- K1: w1 = a[0:D]^T W, w2 = a[D:2D]^T W --------------------------
// 16 blocks x 256 threads. Block b -> 16-col slice. Thread (g=tid>>4, l=tid&15):
// 16 independent W loads (full unroll, MLP=16), BOTH halves share each load.
__global__ __launch_bounds__(256) void k_w12(const float* __restrict__ W,
                                             const float* __restrict__ a) {
    __shared__ float p1[16][17];
    __shared__ float p2[16][17];
    int tid = threadIdx.x;
    int l = tid & 15, g = tid >> 4;
    int col = blockIdx.x * 16 + l;
    int j0 = g * 16;
    float a1 = 0.f, a2 = 0.f;
#pragma unroll
    for (int i = 0; i < 16; i++) {
        float wv = W[(j0 + i) * DD + col];
        a1 += a[j0 + i] * wv;
        a2 += a[DD + j0 + i] * wv;
    }
    p1[g][l] = a1; p2[g][l] = a2;
    __syncthreads();
    if (tid < 32) {
        int half = tid >> 4, c = tid & 15;
        const float (*ps)[17] = half ? p2 : p1;
        float s = 0.f;
#pragma unroll
        for (int r = 0; r < 16; r++) s += ps[r][c];
        g_w12[half * DD + blockIdx.x * 16 + c] = s;
    }
}

// ---------------- K2: one warp per edge: logit sign -> gather tables ------------
__global__ __launch_bounds__(256) void k_edge(const float* __restrict__ x,
                                              const int* __restrict__ dep,
                                              const int* __restrict__ gov) {
    int e = blockIdx.x * 8 + (threadIdx.x >> 5);
    int lane = threadIdx.x & 31;
    if (e >= EE) return;
    int g = gov[e], d = dep[e];

    const float4* x4 = (const float4*)x;
    const float4* w4 = (const float4*)g_w12;
    float4 w1a = w4[lane * 2],      w1b = w4[lane * 2 + 1];
    float4 w2a = w4[64 + lane * 2], w2b = w4[64 + lane * 2 + 1];
    float4 xg0 = x4[g * 64 + lane * 2], xg1 = x4[g * 64 + lane * 2 + 1];
    float4 xd0 = x4[d * 64 + lane * 2], xd1 = x4[d * 64 + lane * 2 + 1];

    float s = dot4(xg0, w1a) + dot4(xg1, w1b) + dot4(xd0, w2a) + dot4(xd1, w2b);
#pragma unroll
    for (int o = 16; o; o >>= 1)
        s += __shfl_xor_sync(0xFFFFFFFFu, s, o);
    if (lane == 0) {
        float coef = (s > 0.f) ? 1.f : (1.f / (float)NN);
        g_cA[d] = 1.f;  g_sA[d] = g;   // h[dep]  = Hx[gov]
        g_cB[g] = coef; g_sB[g] = d;   // h[gov] += coef * Hx[dep]
    }
}

// ---------------- K3: double-buffered fused-gather tf32 GEMM + leaky relu -------
// BM=128, BN=128, BK=32; 512 thr, 16 warps 4(m) x 4(n), warp tile 32x32.
// (r5 structure: register-prefetch A and B, cvt at smem store, 1 bar/step)
#define TSTG (128 * 36)

__global__ __launch_bounds__(512, 1) void k_gemm(
    const float* __restrict__ x, const float* __restrict__ W,
    float* __restrict__ out)
{
    extern __shared__ float sm[];
    float* Asm = sm;              // [2][128*36]
    float* Bsm = sm + 2 * TSTG;   // [2][128*36]

    int tid = threadIdx.x;
    int m0 = blockIdx.y * 128;
    int n0 = blockIdx.x * 128;

    // ---- load mapping: thread -> row (tid>>2), quarter slab (tid&3), 2 f4 each --
    int arow = tid >> 2;
    int aq   = tid & 3;
    int row  = m0 + arow;
    float cA = g_cA[row], cB = g_cB[row];
    int   sA = g_sA[row], sB = g_sB[row];

    const float4* x4 = (const float4*)x;
    const float4* W4 = (const float4*)W;
    int aOff = sA * 64 + aq * 2;
    int bOff = sB * 64 + aq * 2;
    int wOff = (n0 + arow) * 64 + aq * 2;
    int st0  = arow * 36 + aq * 8;

    float4 rg[2], rb[2], rw[2];
#pragma unroll
    for (int j = 0; j < 2; j++) { rg[j] = x4[aOff + j]; rb[j] = x4[bOff + j]; rw[j] = W4[wOff + j]; }

#define STORE_TILE(buf) do {                                                  \
        float* Ad = Asm + (buf) * TSTG + st0;                                 \
        float* Bd = Bsm + (buf) * TSTG + st0;                                 \
        _Pragma("unroll")                                                     \
        for (int j = 0; j < 2; j++) {                                         \
            Ad[j*4+0] = tfbits(cA * rg[j].x + cB * rb[j].x);                  \
            Ad[j*4+1] = tfbits(cA * rg[j].y + cB * rb[j].y);                  \
            Ad[j*4+2] = tfbits(cA * rg[j].z + cB * rb[j].z);                  \
            Ad[j*4+3] = tfbits(cA * rg[j].w + cB * rb[j].w);                  \
            Bd[j*4+0] = tfbits(rw[j].x);                                      \
            Bd[j*4+1] = tfbits(rw[j].y);                                      \
            Bd[j*4+2] = tfbits(rw[j].z);                                      \
            Bd[j*4+3] = tfbits(rw[j].w);                                      \
        }                                                                     \
    } while (0)

    STORE_TILE(0);

    // ---- fragment addressing: 16 warps 4(m) x 4(n), warp tile 32x32 ----
    int wid = tid >> 5, lane = tid & 31;
    int wm  = (wid & 3) * 32;
    int wn  = (wid >> 2) * 32;
    int aRow = wm + (lane & 7) + ((lane & 8) ? 8 : 0);
    int aColF = (lane & 16) ? 4 : 0;
    unsigned aB = su32(Asm + aRow * 36 + aColF);
    int bRow = wn + (lane & 7);
    int bColF = (lane & 8) ? 4 : 0;
    unsigned bB = su32(Bsm + bRow * 36 + bColF);

    float acc[2][4][4];
#pragma unroll
    for (int i = 0; i < 2; i++)
#pragma unroll
        for (int j = 0; j < 4; j++)
#pragma unroll
            for (int v = 0; v < 4; v++) acc[i][j][v] = 0.f;

    __syncthreads();

#pragma unroll 1
    for (int kt = 0; kt < 8; kt++) {
        if (kt < 7) {                    // prefetch next k-slab (hidden under MMAs)
            int kq = (kt + 1) * 8;
#pragma unroll
            for (int j = 0; j < 2; j++) {
                rg[j] = x4[aOff + kq + j];
                rb[j] = x4[bOff + kq + j];
                rw[j] = W4[wOff + kq + j];
            }
        }
        int buf = kt & 1;
        unsigned aS = aB + buf * TSTG * 4;
        unsigned bS = bB + buf * TSTG * 4;
#pragma unroll
        for (int ks = 0; ks < 4; ks++) {
            int k = ks * 8;
            unsigned af[2][4], bf[4][2];
#pragma unroll
            for (int mf = 0; mf < 2; mf++)
                asm volatile("ldmatrix.sync.aligned.m8n8.x4.shared.b16 {%0,%1,%2,%3}, [%4];"
                    : "=r"(af[mf][0]), "=r"(af[mf][1]), "=r"(af[mf][2]), "=r"(af[mf][3])
                    : "r"(aS + (unsigned)((mf * 576 + k) * 4)));
#pragma unroll
            for (int nf = 0; nf < 4; nf++)
                asm volatile("ldmatrix.sync.aligned.m8n8.x2.shared.b16 {%0,%1}, [%2];"
                    : "=r"(bf[nf][0]), "=r"(bf[nf][1])
                    : "r"(bS + (unsigned)((nf * 288 + k) * 4)));
#pragma unroll
            for (int mf = 0; mf < 2; mf++)
#pragma unroll
                for (int nf = 0; nf < 4; nf++)
                    asm volatile(
                        "mma.sync.aligned.m16n8k8.row.col.f32.tf32.tf32.f32 "
                        "{%0,%1,%2,%3}, {%4,%5,%6,%7}, {%8,%9}, {%0,%1,%2,%3};"
                        : "+f"(acc[mf][nf][0]), "+f"(acc[mf][nf][1]),
                          "+f"(acc[mf][nf][2]), "+f"(acc[mf][nf][3])
                        : "r"(af[mf][0]), "r"(af[mf][1]), "r"(af[mf][2]), "r"(af[mf][3]),
                          "r"(bf[nf][0]), "r"(bf[nf][1]));
        }
        if (kt < 7) {
            STORE_TILE(1 - buf);         // opposite buffer: no pre-store sync
            __syncthreads();
        }
    }

    // ---- epilogue: leaky relu, float2 stores ----
    int er = m0 + wm + (lane >> 2);
    int ec = n0 + wn + (lane & 3) * 2;
#pragma unroll
    for (int mf = 0; mf < 2; mf++) {
#pragma unroll
        for (int nf = 0; nf < 4; nf++) {
            float2 v0, v1;
            v0.x = lrelu(acc[mf][nf][0]); v0.y = lrelu(acc[mf][nf][1]);
            v1.x = lrelu(acc[mf][nf][2]); v1.y = lrelu(acc[mf][nf][3]);
            *(float2*)&out[(er + mf * 16) * DD + ec + nf * 8]     = v0;
            *(float2*)&out[(er + mf * 16 + 8) * DD + ec + nf * 8] = v1;
        }
    }
}

// ---------------- launch ---------------------------------------------------------
extern "C" void kernel_launch(void* const* d_in, const int* in_sizes, int n_in,
                              void* d_out, int out_size) {
    const float* x   = (const float*)d_in[0];
    const float* W   = (const float*)d_in[1];
    const float* a   = (const float*)d_in[2];
    const int*   dep = (const int*)d_in[3];
    const int*   gov = (const int*)d_in[4];
    float* out = (float*)d_out;

    int smem = 4 * TSTG * 4;   // 73,728 B
    cudaFuncSetAttribute(k_gemm, cudaFuncAttributeMaxDynamicSharedMemorySize, smem);

    k_w12 <<<16, 256>>>(W, a);
    k_edge<<<1024, 256>>>(x, dep, gov);
    k_gemm<<<dim3(2, 64), 512, smem>>>(x, W, out);
}

// round 9
// speedup vs baseline: 1.4305x; 1.4305x over previous
#include <cuda_runtime.h>

#define DD   256
#define NN   8192
#define EE   8191
#define ALPHA 0.2f
#define GRID 128

// ---------------- scratch (allocation-free __device__ globals, zero-init) -------
__device__ float g_w12[2 * DD];
// per-output-row gather tables: out_row r = lrelu((cA*x[sA] + cB*x[sB]) @ W^T)
__device__ float g_cA[NN];
__device__ float g_cB[NN];
__device__ int   g_sA[NN];
__device__ int   g_sB[NN];
__device__ unsigned g_bar1, g_bar2, g_bar3;   // self-resetting each call

__device__ __forceinline__ unsigned f2tf(float f) {
    unsigned r; asm("cvt.rna.tf32.f32 %0, %1;" : "=r"(r) : "f"(f)); return r;
}
__device__ __forceinline__ float tfbits(float f) { return __uint_as_float(f2tf(f)); }
__device__ __forceinline__ float lrelu(float v) { return v > 0.f ? v : ALPHA * v; }
__device__ __forceinline__ unsigned su32(const void* p) {
    return (unsigned)__cvta_generic_to_shared(p);
}
__device__ __forceinline__ float dot4(float4 a, float4 b) {
    return a.x * b.x + a.y * b.y + a.z * b.z + a.w * b.w;
}
__device__ __forceinline__ void gridbar(unsigned* ctr) {
    __syncthreads();
    if (threadIdx.x == 0) {
        __threadfence();
        atomicAdd(ctr, 1u);
        while (*(volatile unsigned*)ctr < GRID) __nanosleep(32);
        __threadfence();
    }
    __syncthreads();
}

#define TSTG (128 * 36)

__global__ __launch_bounds__(512, 1) void k_fused(
    const float* __restrict__ x, const float* __restrict__ W,
    const float* __restrict__ a,
    const int* __restrict__ dep, const int* __restrict__ gov,
    float* __restrict__ out)
{
    extern __shared__ float sm[];
    int tid = threadIdx.x;
    int blk = blockIdx.x;

    // ================= phase 0: w12 on blocks 0..15 =================
    if (blk < 16) {
        float* p1 = sm;            // [32][16]
        float* p2 = sm + 512;
        int l = tid & 15, g = tid >> 4;      // col-in-slice, j-group (0..31)
        int col = blk * 16 + l;
        int j0 = g * 8;
        float a1 = 0.f, a2 = 0.f;
#pragma unroll
        for (int i = 0; i < 8; i++) {
            float wv = W[(j0 + i) * DD + col];
            a1 += a[j0 + i] * wv;
            a2 += a[DD + j0 + i] * wv;
        }
        p1[g * 16 + l] = a1; p2[g * 16 + l] = a2;
        __syncthreads();
        if (tid < 32) {
            int half = tid >> 4, c = tid & 15;
            const float* ps = half ? p2 : p1;
            float s = 0.f;
#pragma unroll
            for (int r = 0; r < 32; r++) s += ps[r * 16 + c];
            g_w12[half * DD + blk * 16 + c] = s;
        }
    }
    gridbar(&g_bar1);

    // ================= phase 1: edges (2048 warps x 4 edges) =================
    {
        int wid = tid >> 5, lane = tid & 31;
        int gw = blk * 16 + wid;             // 0..2047
        const float4* x4 = (const float4*)x;
        const float4* w4 = (const float4*)g_w12;
        float4 w1a = w4[lane * 2],      w1b = w4[lane * 2 + 1];
        float4 w2a = w4[64 + lane * 2], w2b = w4[64 + lane * 2 + 1];
        int eb = gw * 4;
        int ge[4], de[4];
#pragma unroll
        for (int i = 0; i < 4; i++) {
            int e = eb + i;
            ge[i] = (e < EE) ? gov[e] : 0;
            de[i] = (e < EE) ? dep[e] : 0;
        }
#pragma unroll
        for (int i = 0; i < 4; i++) {
            if (eb + i >= EE) break;
            int g = ge[i], d = de[i];
            float4 xg0 = x4[g * 64 + lane * 2], xg1 = x4[g * 64 + lane * 2 + 1];
            float4 xd0 = x4[d * 64 + lane * 2], xd1 = x4[d * 64 + lane * 2 + 1];
            float s = dot4(xg0, w1a) + dot4(xg1, w1b) + dot4(xd0, w2a) + dot4(xd1, w2b);
#pragma unroll
            for (int o = 16; o; o >>= 1)
                s += __shfl_xor_sync(0xFFFFFFFFu, s, o);
            if (lane == 0) {
                float coef = (s > 0.f) ? 1.f : (1.f / (float)NN);
                g_cA[d] = 1.f;  g_sA[d] = g;   // h[dep]  = Hx[gov]
                g_cB[g] = coef; g_sB[g] = d;   // h[gov] += coef * Hx[dep]
            }
        }
    }
    gridbar(&g_bar2);

    // ================= phase 2: fused-gather tf32 GEMM (r5 body) =============
    {
        float* Asm = sm;              // [2][128*36]
        float* Bsm = sm + 2 * TSTG;   // [2][128*36]
        int m0 = (blk >> 1) * 128;
        int n0 = (blk & 1) * 128;

        int arow = tid >> 2;
        int aq   = tid & 3;
        int row  = m0 + arow;
        float cA = g_cA[row], cB = g_cB[row];
        int   sA = g_sA[row], sB = g_sB[row];

        const float4* x4 = (const float4*)x;
        const float4* W4 = (const float4*)W;
        int aOff = sA * 64 + aq * 2;
        int bOff = sB * 64 + aq * 2;
        int wOff = (n0 + arow) * 64 + aq * 2;
        int st0  = arow * 36 + aq * 8;

        float4 rg[2], rb[2], rw[2];
#pragma unroll
        for (int j = 0; j < 2; j++) { rg[j] = x4[aOff + j]; rb[j] = x4[bOff + j]; rw[j] = W4[wOff + j]; }

#define STORE_TILE(buf) do {                                                  \
        float* Ad = Asm + (buf) * TSTG + st0;                                 \
        float* Bd = Bsm + (buf) * TSTG + st0;                                 \
        _Pragma("unroll")                                                     \
        for (int j = 0; j < 2; j++) {                                         \
            Ad[j*4+0] = tfbits(cA * rg[j].x + cB * rb[j].x);                  \
            Ad[j*4+1] = tfbits(cA * rg[j].y + cB * rb[j].y);                  \
            Ad[j*4+2] = tfbits(cA * rg[j].z + cB * rb[j].z);                  \
            Ad[j*4+3] = tfbits(cA * rg[j].w + cB * rb[j].w);                  \
            Bd[j*4+0] = tfbits(rw[j].x);                                      \
            Bd[j*4+1] = tfbits(rw[j].y);                                      \
            Bd[j*4+2] = tfbits(rw[j].z);                                      \
            Bd[j*4+3] = tfbits(rw[j].w);                                      \
        }                                                                     \
    } while (0)

        STORE_TILE(0);

        int wid = tid >> 5, lane = tid & 31;
        int wm  = (wid & 3) * 32;
        int wn  = (wid >> 2) * 32;
        int aRow = wm + (lane & 7) + ((lane & 8) ? 8 : 0);
        int aColF = (lane & 16) ? 4 : 0;
        unsigned aB = su32(Asm + aRow * 36 + aColF);
        int bRow = wn + (lane & 7);
        int bColF = (lane & 8) ? 4 : 0;
        unsigned bB = su32(Bsm + bRow * 36 + bColF);

        float acc[2][4][4];
#pragma unroll
        for (int i = 0; i < 2; i++)
#pragma unroll
            for (int j = 0; j < 4; j++)
#pragma unroll
                for (int v = 0; v < 4; v++) acc[i][j][v] = 0.f;

        __syncthreads();

#pragma unroll 1
        for (int kt = 0; kt < 8; kt++) {
            if (kt < 7) {                    // prefetch next k-slab
                int kq = (kt + 1) * 8;
#pragma unroll
                for (int j = 0; j < 2; j++) {
                    rg[j] = x4[aOff + kq + j];
                    rb[j] = x4[bOff + kq + j];
                    rw[j] = W4[wOff + kq + j];
                }
            }
            int buf = kt & 1;
            unsigned aS = aB + buf * TSTG * 4;
            unsigned bS = bB + buf * TSTG * 4;
#pragma unroll
            for (int ks = 0; ks < 4; ks++) {
                int k = ks * 8;
                unsigned af[2][4], bf[4][2];
#pragma unroll
                for (int mf = 0; mf < 2; mf++)
                    asm volatile("ldmatrix.sync.aligned.m8n8.x4.shared.b16 {%0,%1,%2,%3}, [%4];"
                        : "=r"(af[mf][0]), "=r"(af[mf][1]), "=r"(af[mf][2]), "=r"(af[mf][3])
                        : "r"(aS + (unsigned)((mf * 576 + k) * 4)));
#pragma unroll
                for (int nf = 0; nf < 4; nf++)
                    asm volatile("ldmatrix.sync.aligned.m8n8.x2.shared.b16 {%0,%1}, [%2];"
                        : "=r"(bf[nf][0]), "=r"(bf[nf][1])
                        : "r"(bS + (unsigned)((nf * 288 + k) * 4)));
#pragma unroll
                for (int mf = 0; mf < 2; mf++)
#pragma unroll
                    for (int nf = 0; nf < 4; nf++)
                        asm volatile(
                            "mma.sync.aligned.m16n8k8.row.col.f32.tf32.tf32.f32 "
                            "{%0,%1,%2,%3}, {%4,%5,%6,%7}, {%8,%9}, {%0,%1,%2,%3};"
                            : "+f"(acc[mf][nf][0]), "+f"(acc[mf][nf][1]),
                              "+f"(acc[mf][nf][2]), "+f"(acc[mf][nf][3])
                            : "r"(af[mf][0]), "r"(af[mf][1]), "r"(af[mf][2]), "r"(af[mf][3]),
                              "r"(bf[nf][0]), "r"(bf[nf][1]));
            }
            if (kt < 7) {
                STORE_TILE(1 - buf);
                __syncthreads();
            }
        }

        int er = m0 + wm + (lane >> 2);
        int ec = n0 + wn + (lane & 3) * 2;
#pragma unroll
        for (int mf = 0; mf < 2; mf++) {
#pragma unroll
            for (int nf = 0; nf < 4; nf++) {
                float2 v0, v1;
                v0.x = lrelu(acc[mf][nf][0]); v0.y = lrelu(acc[mf][nf][1]);
                v1.x = lrelu(acc[mf][nf][2]); v1.y = lrelu(acc[mf][nf][3]);
                *(float2*)&out[(er + mf * 16) * DD + ec + nf * 8]     = v0;
                *(float2*)&out[(er + mf * 16 + 8) * DD + ec + nf * 8] = v1;
            }
        }
    }

    // ---- reset barrier counters for next graph replay (last block does it) ----
    __syncthreads();
    if (tid == 0) {
        unsigned old = atomicAdd(&g_bar3, 1u);
        if (old == GRID - 1) {
            g_bar1 = 0; g_bar2 = 0; g_bar3 = 0;
            __threadfence();
        }
    }
}

// ---------------- launch ---------------------------------------------------------
extern "C" void kernel_launch(void* const* d_in, const int* in_sizes, int n_in,
                              void* d_out, int out_size) {
    const float* x   = (const float*)d_in[0];
    const float* W   = (const float*)d_in[1];
    const float* a   = (const float*)d_in[2];
    const int*   dep = (const int*)d_in[3];
    const int*   gov = (const int*)d_in[4];
    float* out = (float*)d_out;

    int smem = 4 * TSTG * 4;   // 73,728 B
    cudaFuncSetAttribute(k_fused, cudaFuncAttributeMaxDynamicSharedMemorySize, smem);

    k_fused<<<GRID, 512, smem>>>(x, W, a, dep, gov, out);
}